// round 3
// baseline (speedup 1.0000x reference)
#include <cuda_runtime.h>
#include <math.h>
#include <float.h>

#define NB      64
#define TOKENS  784
#define DIM     768
#define FH      28
#define IMG     448
#define TOPK    8
#define PATCH   16

__device__ float g_dist[NB * TOKENS];
__device__ int   g_box[NB][4];   // x0, x1, y0, y1

// ---------------------------------------------------------------------------
// Kernel 1: score = dot(g, l) / ||l||  (g-norm is a positive per-batch
// constant -> ordering identical to cosine). grid (64,16) x 256: 1024 blocks
// -> ~7 blocks/SM, occ ~86%. Streams 154 MB of x.
// ---------------------------------------------------------------------------
__global__ void sim_kernel(const float* __restrict__ x) {
    int b = blockIdx.x;
    int s = blockIdx.y;                       // 0..15 -> rows [s*49, s*49+49)
    const float* xb = x + (size_t)b * 785 * DIM;

    __shared__ float4 g_sh[DIM / 4];          // CLS token, 3 KB
    int tid = threadIdx.x;
    if (tid < DIM / 4) g_sh[tid] = ((const float4*)xb)[tid];
    __syncthreads();

    int warp = tid >> 5, lane = tid & 31;
    int r0 = s * 49;
    for (int r = r0 + warp; r < r0 + 49; r += 8) {
        const float4* lv = (const float4*)(xb + (size_t)(1 + r) * DIM);
        float dot = 0.f, nrm = 0.f;
#pragma unroll
        for (int j = 0; j < 6; ++j) {         // 6*32*4 = 768 elems
            float4 l = lv[lane + 32 * j];
            float4 g = g_sh[lane + 32 * j];
            dot += l.x * g.x + l.y * g.y + l.z * g.z + l.w * g.w;
            nrm += l.x * l.x + l.y * l.y + l.z * l.z + l.w * l.w;
        }
#pragma unroll
        for (int off = 16; off; off >>= 1) {
            dot += __shfl_xor_sync(0xffffffffu, dot, off);
            nrm += __shfl_xor_sync(0xffffffffu, nrm, off);
        }
        if (lane == 0) {
            float ln = fmaxf(sqrtf(nrm), 1e-8f);
            g_dist[b * TOKENS + r] = dot / ln;
        }
    }
}

// ---------------------------------------------------------------------------
// Kernel 2: top-8 argmax rounds (stable ties -> lower index), bounding box.
// One warp per batch.
// ---------------------------------------------------------------------------
__global__ void topk_kernel() {
    int b = blockIdx.x;
    int lane = threadIdx.x;                   // 32 threads
    __shared__ float dist[TOKENS];
    for (int i = lane; i < TOKENS; i += 32) dist[i] = g_dist[b * TOKENS + i];
    __syncwarp();

    int minx = FH, maxx = -1, miny = FH, maxy = -1;
#pragma unroll 1
    for (int k = 0; k < TOPK; ++k) {
        float best = -FLT_MAX; int bi = TOKENS;
        for (int i = lane; i < TOKENS; i += 32) {
            float v = dist[i];
            if (v > best) { best = v; bi = i; }   // strict > keeps lowest idx
        }
#pragma unroll
        for (int off = 16; off; off >>= 1) {
            float ov = __shfl_xor_sync(0xffffffffu, best, off);
            int   oi = __shfl_xor_sync(0xffffffffu, bi,   off);
            if (ov > best || (ov == best && oi < bi)) { best = ov; bi = oi; }
        }
        if (lane == 0) dist[bi] = -FLT_MAX;
        __syncwarp();
        int ix = bi / FH, iy = bi % FH;
        minx = min(minx, ix); maxx = max(maxx, ix);
        miny = min(miny, iy); maxy = max(maxy, iy);
    }
    if (lane == 0) {
        int x_i = minx * PATCH, x_f = maxx * PATCH;
        int y_i = miny * PATCH, y_f = maxy * PATCH;
        g_box[b][0] = max(x_i, 0);
        g_box[b][1] = min(max(x_f, x_i + PATCH), IMG);
        g_box[b][2] = max(y_i, 0);
        g_box[b][3] = min(max(y_f, y_i + PATCH), IMG);
    }
}

// ---------------------------------------------------------------------------
// Kernel 3: bilinear crop-resize (align_corners=True), smem row-staged.
// One block per output row (b, c, ty): stage the two source-row segments
// [y0, y1) into shared via coalesced float4 LDGs (y0, y1 multiples of 16 ->
// 64B aligned, width multiple of 16), then all 4-tap gathers come from LDS.
// 8x fewer global load instructions than the per-pixel-LDG version.
// ---------------------------------------------------------------------------
__global__ void resize_kernel(const float* __restrict__ images,
                              float* __restrict__ out) {
    int blk = blockIdx.x;
    int ty = blk % IMG;
    int t  = blk / IMG;
    int c  = t % 3;
    int b  = t / 3;

    __shared__ float s0[IMG];
    __shared__ float s1[IMG];

    int4 bx = *(const int4*)&g_box[b][0];
    int x0 = bx.x, x1 = bx.y, y0 = bx.z, y1 = bx.w;

    const float scale = 1.0f / (float)(IMG - 1);
    float h = (float)(x1 - x0), w = (float)(y1 - y0);

    // vertical source rows for this output row (indices in-range by
    // construction: sy in [x0, x1-1])
    float sy  = (float)x0 + (float)ty * (h - 1.0f) * scale;
    int   ylo = (int)floorf(sy);
    int   yhi = min(ylo + 1, x1 - 1);
    float wy  = sy - (float)ylo;

    const float* src = images + ((size_t)(b * 3 + c)) * IMG * IMG;
    const float4* r0 = (const float4*)(src + (size_t)ylo * IMG + y0);
    const float4* r1 = (const float4*)(src + (size_t)yhi * IMG + y0);

    int w4 = (y1 - y0) >> 2;                  // width is a multiple of 16
    int tid = threadIdx.x;
    for (int i = tid; i < 2 * w4; i += 128) {
        if (i < w4) ((float4*)s0)[i]      = __ldg(r0 + i);
        else        ((float4*)s1)[i - w4] = __ldg(r1 + (i - w4));
    }
    __syncthreads();

    if (tid < IMG / 4) {
        float wstep = (w - 1.0f) * scale;
        float4 res;
        float* rp = (float*)&res;
#pragma unroll
        for (int k = 0; k < 4; ++k) {
            int tx = tid * 4 + k;
            float sx  = (float)y0 + (float)tx * wstep;
            int   xlo = (int)floorf(sx);
            int   xhi = min(xlo + 1, y1 - 1);
            float wx  = sx - (float)xlo;
            int i0 = xlo - y0, i1 = xhi - y0; // in [0, w)
            float a  = s0[i0], bb = s0[i1];
            float cc = s1[i0], dd = s1[i1];
            rp[k] = (1.f - wy) * (1.f - wx) * a
                  + (1.f - wy) * wx         * bb
                  + wy         * (1.f - wx) * cc
                  + wy         * wx         * dd;
        }
        float4* orow = (float4*)(out + (((size_t)(b * 3 + c)) * IMG + ty) * IMG);
        orow[tid] = res;
    }
}

// ---------------------------------------------------------------------------
extern "C" void kernel_launch(void* const* d_in, const int* in_sizes, int n_in,
                              void* d_out, int out_size) {
    const float* x      = (const float*)d_in[0];
    const float* images = (const float*)d_in[1];
    const int X_ELEMS   = NB * 785 * DIM;
    if (n_in >= 2 && in_sizes[0] != X_ELEMS) {
        x      = (const float*)d_in[1];
        images = (const float*)d_in[0];
    }
    float* out = (float*)d_out;

    dim3 g1(NB, 16);
    sim_kernel<<<g1, 256>>>(x);
    topk_kernel<<<NB, 32>>>();
    resize_kernel<<<NB * 3 * IMG, 128>>>(images, out);
}

// round 4
// speedup vs baseline: 1.2585x; 1.2585x over previous
#include <cuda_runtime.h>
#include <math.h>
#include <float.h>

#define NB      64
#define TOKENS  784
#define DIM     768
#define FH      28
#define IMG     448
#define TOPK    8
#define PATCH   16

__device__ float g_dist[NB * TOKENS];
__device__ int   g_box[NB][4];   // x0, x1, y0, y1

// ---------------------------------------------------------------------------
// Kernel 1: score = dot(g, l) / ||l||  (g-norm positive per-batch constant
// -> same ordering as cosine). grid (64,7) x 256. Each warp processes 2 rows
// per iteration -> 12 independent float4 LDGs in flight (2x MLP vs R1/R2).
// ---------------------------------------------------------------------------
__global__ void sim_kernel(const float* __restrict__ x) {
    int b = blockIdx.x;
    int s = blockIdx.y;                       // 0..6 -> 112 rows per block
    const float* xb = x + (size_t)b * 785 * DIM;

    __shared__ float4 g_sh[DIM / 4];          // CLS token, 3 KB
    int tid = threadIdx.x;
    if (tid < DIM / 4) g_sh[tid] = ((const float4*)xb)[tid];
    __syncthreads();

    int warp = tid >> 5, lane = tid & 31;
    int base = s * 112 + warp * 14;           // 14 rows per warp, as 7 pairs
#pragma unroll 1
    for (int k = 0; k < 7; ++k) {
        int r = base + 2 * k;
        const float4* l0 = (const float4*)(xb + (size_t)(1 + r) * DIM);
        const float4* l1 = (const float4*)(xb + (size_t)(2 + r) * DIM);
        float d0 = 0.f, n0 = 0.f, d1 = 0.f, n1 = 0.f;
#pragma unroll
        for (int j = 0; j < 6; ++j) {
            float4 a = l0[lane + 32 * j];
            float4 c = l1[lane + 32 * j];
            float4 g = g_sh[lane + 32 * j];
            d0 += a.x * g.x + a.y * g.y + a.z * g.z + a.w * g.w;
            n0 += a.x * a.x + a.y * a.y + a.z * a.z + a.w * a.w;
            d1 += c.x * g.x + c.y * g.y + c.z * g.z + c.w * g.w;
            n1 += c.x * c.x + c.y * c.y + c.z * c.z + c.w * c.w;
        }
#pragma unroll
        for (int off = 16; off; off >>= 1) {
            d0 += __shfl_xor_sync(0xffffffffu, d0, off);
            n0 += __shfl_xor_sync(0xffffffffu, n0, off);
            d1 += __shfl_xor_sync(0xffffffffu, d1, off);
            n1 += __shfl_xor_sync(0xffffffffu, n1, off);
        }
        if (lane == 0) {
            g_dist[b * TOKENS + r]     = d0 / fmaxf(sqrtf(n0), 1e-8f);
            g_dist[b * TOKENS + r + 1] = d1 / fmaxf(sqrtf(n1), 1e-8f);
        }
    }
}

// ---------------------------------------------------------------------------
// Kernel 2: top-8 argmax rounds (stable ties -> lower index), bounding box.
// ---------------------------------------------------------------------------
__global__ void topk_kernel() {
    int b = blockIdx.x;
    int lane = threadIdx.x;                   // 32 threads
    __shared__ float dist[TOKENS];
    for (int i = lane; i < TOKENS; i += 32) dist[i] = g_dist[b * TOKENS + i];
    __syncwarp();

    int minx = FH, maxx = -1, miny = FH, maxy = -1;
#pragma unroll 1
    for (int k = 0; k < TOPK; ++k) {
        float best = -FLT_MAX; int bi = TOKENS;
        for (int i = lane; i < TOKENS; i += 32) {
            float v = dist[i];
            if (v > best) { best = v; bi = i; }   // strict > keeps lowest idx
        }
#pragma unroll
        for (int off = 16; off; off >>= 1) {
            float ov = __shfl_xor_sync(0xffffffffu, best, off);
            int   oi = __shfl_xor_sync(0xffffffffu, bi,   off);
            if (ov > best || (ov == best && oi < bi)) { best = ov; bi = oi; }
        }
        if (lane == 0) dist[bi] = -FLT_MAX;
        __syncwarp();
        int ix = bi / FH, iy = bi % FH;
        minx = min(minx, ix); maxx = max(maxx, ix);
        miny = min(miny, iy); maxy = max(maxy, iy);
    }
    if (lane == 0) {
        int x_i = minx * PATCH, x_f = maxx * PATCH;
        int y_i = miny * PATCH, y_f = maxy * PATCH;
        g_box[b][0] = max(x_i, 0);
        g_box[b][1] = min(max(x_f, x_i + PATCH), IMG);
        g_box[b][2] = max(y_i, 0);
        g_box[b][3] = min(max(y_f, y_i + PATCH), IMG);
    }
}

// ---------------------------------------------------------------------------
// Kernel 3: bilinear crop-resize, 2D-tiled with vertical reuse.
// Block = (b, c, group of 8 output rows). Vertical slope <= 1, so 8 output
// rows touch at most 9 source rows: stage rows [rlo, rhi] x cols [y0, y1)
// once into smem (coalesced float4; y0 multiple of 16 -> aligned), then all
// 8x448 outputs interpolate from LDS. ~14 px/thread for ILP.
// ---------------------------------------------------------------------------
#define ROWG 8
__global__ void __launch_bounds__(256) resize_kernel(
        const float* __restrict__ images, float* __restrict__ out) {
    int blk = blockIdx.x;
    int g  = blk % (IMG / ROWG);
    int t  = blk / (IMG / ROWG);
    int c  = t % 3;
    int b  = t / 3;
    int ty0 = g * ROWG;

    __shared__ float s[9 * IMG];              // <= 16.1 KB

    int4 bx = *(const int4*)&g_box[b][0];
    int x0 = bx.x, x1 = bx.y, y0 = bx.z, y1 = bx.w;

    const float scale = 1.0f / (float)(IMG - 1);
    float hstep = ((float)(x1 - x0) - 1.0f) * scale;   // vertical slope <= 1
    float wstep = ((float)(y1 - y0) - 1.0f) * scale;

    // source row range for output rows [ty0, ty0+7]
    int rlo = (int)floorf((float)x0 + (float)ty0 * hstep);
    int rhi = min((int)floorf((float)x0 + (float)(ty0 + ROWG - 1) * hstep) + 1,
                  x1 - 1);
    int nrows = rhi - rlo + 1;                // <= 9
    int w  = y1 - y0;                         // multiple of 16
    int w4 = w >> 2;

    // Phase 1: stage source rows (coalesced float4)
    const float* src = images + (size_t)(b * 3 + c) * IMG * IMG;
    int tid = threadIdx.x;
    int total4 = nrows * w4;
    for (int i = tid; i < total4; i += 256) {
        int rr = i / w4;
        int cc = i - rr * w4;
        ((float4*)s)[rr * w4 + cc] =
            __ldg((const float4*)(src + (size_t)(rlo + rr) * IMG + y0) + cc);
    }
    __syncthreads();

    // Phase 2: 8*448/4 = 896 output float4s
    float* orow_base = out + (size_t)(b * 3 + c) * IMG * IMG;
#pragma unroll 1
    for (int j = tid; j < ROWG * (IMG / 4); j += 256) {
        int tyl = j / (IMG / 4);
        int txq = j - tyl * (IMG / 4);
        int ty  = ty0 + tyl;

        float sy  = (float)x0 + (float)ty * hstep;
        int   ylo = (int)floorf(sy);
        int   yhi = min(ylo + 1, x1 - 1);
        float wy  = sy - (float)ylo;
        const float* r0 = s + (ylo - rlo) * w;
        const float* r1 = s + (yhi - rlo) * w;

        float4 res;
        float* rp = (float*)&res;
#pragma unroll
        for (int k = 0; k < 4; ++k) {
            int tx = txq * 4 + k;
            float sx  = (float)y0 + (float)tx * wstep;
            int   xlo = (int)floorf(sx);
            int   xhi = min(xlo + 1, y1 - 1);
            float wx  = sx - (float)xlo;
            int i0 = xlo - y0, i1 = xhi - y0;
            float a  = r0[i0], bb = r0[i1];
            float cc = r1[i0], dd = r1[i1];
            rp[k] = (1.f - wy) * (1.f - wx) * a
                  + (1.f - wy) * wx         * bb
                  + wy         * (1.f - wx) * cc
                  + wy         * wx         * dd;
        }
        ((float4*)(orow_base + (size_t)ty * IMG))[txq] = res;
    }
}

// ---------------------------------------------------------------------------
extern "C" void kernel_launch(void* const* d_in, const int* in_sizes, int n_in,
                              void* d_out, int out_size) {
    const float* x      = (const float*)d_in[0];
    const float* images = (const float*)d_in[1];
    const int X_ELEMS   = NB * 785 * DIM;
    if (n_in >= 2 && in_sizes[0] != X_ELEMS) {
        x      = (const float*)d_in[1];
        images = (const float*)d_in[0];
    }
    float* out = (float*)d_out;

    dim3 g1(NB, 7);
    sim_kernel<<<g1, 256>>>(x);
    topk_kernel<<<NB, 32>>>();
    resize_kernel<<<NB * 3 * (IMG / ROWG), 256>>>(images, out);
}

// round 5
// speedup vs baseline: 1.3679x; 1.0869x over previous
#include <cuda_runtime.h>
#include <math.h>
#include <float.h>

#define NB      64
#define TOKENS  784
#define DIM     768
#define FH      28
#define IMG     448
#define TOPK    8
#define PATCH   16

__device__ float g_dist[NB * TOKENS];
__device__ int   g_box[NB][4];   // x0, x1, y0, y1

// ---------------------------------------------------------------------------
// Kernel 1: score = dot(g, l) / ||l||  (g-norm positive per-batch constant
// -> same ordering as cosine). grid (64,49) x 256: 3136 blocks (~21/SM,
// occ ~95%), each warp does exactly 2 rows -> 12 independent LDG.128 in
// flight per warp AND high SM-wide concurrency.
// ---------------------------------------------------------------------------
__global__ void __launch_bounds__(256) sim_kernel(const float* __restrict__ x) {
    int b = blockIdx.x;
    int s = blockIdx.y;                       // 0..48 -> 16 rows per block
    const float* xb = x + (size_t)b * 785 * DIM;

    __shared__ float4 g_sh[DIM / 4];          // CLS token, 3 KB
    int tid = threadIdx.x;
    if (tid < DIM / 4) g_sh[tid] = ((const float4*)xb)[tid];
    __syncthreads();

    int warp = tid >> 5, lane = tid & 31;
    int r = s * 16 + warp * 2;                // this warp's row pair
    const float4* l0 = (const float4*)(xb + (size_t)(1 + r) * DIM);
    const float4* l1 = (const float4*)(xb + (size_t)(2 + r) * DIM);
    float d0 = 0.f, n0 = 0.f, d1 = 0.f, n1 = 0.f;
#pragma unroll
    for (int j = 0; j < 6; ++j) {
        float4 a = l0[lane + 32 * j];
        float4 c = l1[lane + 32 * j];
        float4 g = g_sh[lane + 32 * j];
        d0 += a.x * g.x + a.y * g.y + a.z * g.z + a.w * g.w;
        n0 += a.x * a.x + a.y * a.y + a.z * a.z + a.w * a.w;
        d1 += c.x * g.x + c.y * g.y + c.z * g.z + c.w * g.w;
        n1 += c.x * c.x + c.y * c.y + c.z * c.z + c.w * c.w;
    }
#pragma unroll
    for (int off = 16; off; off >>= 1) {
        d0 += __shfl_xor_sync(0xffffffffu, d0, off);
        n0 += __shfl_xor_sync(0xffffffffu, n0, off);
        d1 += __shfl_xor_sync(0xffffffffu, d1, off);
        n1 += __shfl_xor_sync(0xffffffffu, n1, off);
    }
    if (lane == 0) {
        g_dist[b * TOKENS + r]     = d0 / fmaxf(sqrtf(n0), 1e-8f);
        g_dist[b * TOKENS + r + 1] = d1 / fmaxf(sqrtf(n1), 1e-8f);
    }
}

// ---------------------------------------------------------------------------
// Kernel 2: top-8 argmax rounds (stable ties -> lower index), bounding box.
// ---------------------------------------------------------------------------
__global__ void topk_kernel() {
    int b = blockIdx.x;
    int lane = threadIdx.x;                   // 32 threads
    __shared__ float dist[TOKENS];
    for (int i = lane; i < TOKENS; i += 32) dist[i] = g_dist[b * TOKENS + i];
    __syncwarp();

    int minx = FH, maxx = -1, miny = FH, maxy = -1;
#pragma unroll 1
    for (int k = 0; k < TOPK; ++k) {
        float best = -FLT_MAX; int bi = TOKENS;
        for (int i = lane; i < TOKENS; i += 32) {
            float v = dist[i];
            if (v > best) { best = v; bi = i; }   // strict > keeps lowest idx
        }
#pragma unroll
        for (int off = 16; off; off >>= 1) {
            float ov = __shfl_xor_sync(0xffffffffu, best, off);
            int   oi = __shfl_xor_sync(0xffffffffu, bi,   off);
            if (ov > best || (ov == best && oi < bi)) { best = ov; bi = oi; }
        }
        if (lane == 0) dist[bi] = -FLT_MAX;
        __syncwarp();
        int ix = bi / FH, iy = bi % FH;
        minx = min(minx, ix); maxx = max(maxx, ix);
        miny = min(miny, iy); maxy = max(maxy, iy);
    }
    if (lane == 0) {
        int x_i = minx * PATCH, x_f = maxx * PATCH;
        int y_i = miny * PATCH, y_f = maxy * PATCH;
        g_box[b][0] = max(x_i, 0);
        g_box[b][1] = min(max(x_f, x_i + PATCH), IMG);
        g_box[b][2] = max(y_i, 0);
        g_box[b][3] = min(max(y_f, y_i + PATCH), IMG);
    }
}

// ---------------------------------------------------------------------------
// Kernel 3: separable bilinear crop-resize.
// Block = (b, c, 8 output rows); vertical slope <= 1 -> at most 9 source
// rows. Phase 1: stage source rows [rlo..rhi] x [y0,y1) (coalesced float4).
// Phase 2: horizontal lerp of those rows into hrow[r][448] (xlo/wx depend
// only on tx -> shared by all rows). Phase 3: per output float4 just
// 2 x LDS.128 + 4 FMA + STG.128 (vertical lerp) -> ~5x fewer instructions
// and ~4x fewer scalar smem gathers than the 4-tap version.
// ---------------------------------------------------------------------------
#define ROWG 8
__global__ void __launch_bounds__(256) resize_kernel(
        const float* __restrict__ images, float* __restrict__ out) {
    int blk = blockIdx.x;
    int g  = blk % (IMG / ROWG);
    int t  = blk / (IMG / ROWG);
    int c  = t % 3;
    int b  = t / 3;
    int ty0 = g * ROWG;

    __shared__ float s[9 * IMG];              // 16.1 KB staged source
    __shared__ float hrow[9 * IMG];           // 16.1 KB h-interpolated rows

    int4 bx = *(const int4*)&g_box[b][0];
    int x0 = bx.x, x1 = bx.y, y0 = bx.z, y1 = bx.w;

    const float scale = 1.0f / (float)(IMG - 1);
    float hstep = ((float)(x1 - x0) - 1.0f) * scale;   // <= 1
    float wstep = ((float)(y1 - y0) - 1.0f) * scale;

    int rlo = (int)floorf((float)x0 + (float)ty0 * hstep);
    int rhi = min((int)floorf((float)x0 + (float)(ty0 + ROWG - 1) * hstep) + 1,
                  x1 - 1);
    int nrows = rhi - rlo + 1;                // <= 9
    int w  = y1 - y0;                         // multiple of 16
    int w4 = w >> 2;

    // Phase 1: stage source rows
    const float* src = images + (size_t)(b * 3 + c) * IMG * IMG;
    int tid = threadIdx.x;
    for (int i = tid; i < nrows * w4; i += 256) {
        int rr = i / w4;
        int cc = i - rr * w4;
        ((float4*)s)[rr * (IMG / 4) + cc] =
            __ldg((const float4*)(src + (size_t)(rlo + rr) * IMG + y0) + cc);
    }
    __syncthreads();

    // Phase 2: horizontal lerp (xlo/wx per-column, shared across rows)
    for (int col = tid; col < IMG; col += 256) {
        float sx  = (float)y0 + (float)col * wstep;
        int   xlo = (int)floorf(sx);
        int   xhi = min(xlo + 1, y1 - 1);
        float wx  = sx - (float)xlo;
        int i0 = xlo - y0, i1 = xhi - y0;
#pragma unroll
        for (int rr = 0; rr < 9; ++rr) {
            if (rr < nrows) {
                float a = s[rr * IMG + i0];
                float bv = s[rr * IMG + i1];
                hrow[rr * IMG + col] = a + wx * (bv - a);
            }
        }
    }
    __syncthreads();

    // Phase 3: vertical lerp, float4-vectorized
    float* obase = out + (size_t)(b * 3 + c) * IMG * IMG;
#pragma unroll 1
    for (int j = tid; j < ROWG * (IMG / 4); j += 256) {
        int tyl = j / (IMG / 4);
        int txq = j - tyl * (IMG / 4);
        int ty  = ty0 + tyl;

        float sy  = (float)x0 + (float)ty * hstep;
        int   ylo = (int)floorf(sy);
        int   yhi = min(ylo + 1, x1 - 1);
        float wy  = sy - (float)ylo;

        float4 h0 = ((const float4*)(hrow + (ylo - rlo) * IMG))[txq];
        float4 h1 = ((const float4*)(hrow + (yhi - rlo) * IMG))[txq];
        float4 res;
        res.x = h0.x + wy * (h1.x - h0.x);
        res.y = h0.y + wy * (h1.y - h0.y);
        res.z = h0.z + wy * (h1.z - h0.z);
        res.w = h0.w + wy * (h1.w - h0.w);
        ((float4*)(obase + (size_t)ty * IMG))[txq] = res;
    }
}

// ---------------------------------------------------------------------------
extern "C" void kernel_launch(void* const* d_in, const int* in_sizes, int n_in,
                              void* d_out, int out_size) {
    const float* x      = (const float*)d_in[0];
    const float* images = (const float*)d_in[1];
    const int X_ELEMS   = NB * 785 * DIM;
    if (n_in >= 2 && in_sizes[0] != X_ELEMS) {
        x      = (const float*)d_in[1];
        images = (const float*)d_in[0];
    }
    float* out = (float*)d_out;

    dim3 g1(NB, 49);
    sim_kernel<<<g1, 256>>>(x);
    topk_kernel<<<NB, 32>>>();
    resize_kernel<<<NB * 3 * (IMG / ROWG), 256>>>(images, out);
}